// round 1
// baseline (speedup 1.0000x reference)
#include <cuda_runtime.h>
#include <cuda_bf16.h>

// Problem constants
constexpr int B_ROWS  = 1024;
constexpr int L_COLS  = 4096;
constexpr int THREADS = 512;           // threads per row-block
constexpr int PER     = L_COLS / THREADS;  // 8 elements per thread
constexpr float INV_TAU = 1.0f / 0.85f;

// Per-row partial results (no device allocation allowed -> __device__ global)
__device__ float g_row[B_ROWS];

// One block per row:
//  1) vector-load 8 labels/thread, block scan -> exclusive prefix count + total T
//  2) fused sweep: f1 = 2c/(k+T); r = f1/tau; accumulate S1 = sum exp(r),
//     S2 = sum exp(r)*(r - log p)
//  3) row result = S2/S1 - log(S1)
__global__ __launch_bounds__(THREADS, 2)
void divloss_row_kernel(const float* __restrict__ p_in,
                        const int*   __restrict__ lab_in) {
    const int row  = blockIdx.x;
    const int t    = threadIdx.x;
    const int lane = t & 31;
    const int warp = t >> 5;

    const int4*   lab = reinterpret_cast<const int4*>(lab_in + (size_t)row * L_COLS);
    const float4* pv  = reinterpret_cast<const float4*>(p_in  + (size_t)row * L_COLS);

    // ---- load 8 labels (two int4) ----
    int4 la = lab[t * 2 + 0];
    int4 lb = lab[t * 2 + 1];
    int v[PER] = { la.x, la.y, la.z, la.w, lb.x, lb.y, lb.z, lb.w };

    int local = 0;
#pragma unroll
    for (int i = 0; i < PER; ++i) local += v[i];

    // ---- block scan of per-thread sums ----
    // warp-level inclusive scan
    int x = local;
#pragma unroll
    for (int o = 1; o < 32; o <<= 1) {
        int y = __shfl_up_sync(0xffffffffu, x, o);
        if (lane >= o) x += y;
    }

    __shared__ int s_warp[16];
    __shared__ int s_off[17];
    if (lane == 31) s_warp[warp] = x;
    __syncthreads();
    if (t == 0) {
        int acc = 0;
#pragma unroll
        for (int w = 0; w < 16; ++w) { s_off[w] = acc; acc += s_warp[w]; }
        s_off[16] = acc;   // total positives T
    }
    __syncthreads();

    const int   T  = s_off[16];
    const float Tf = (float)T;
    int c = s_off[warp] + (x - local);   // exclusive prefix count for this chunk

    // ---- fused f1 / softmax-KL sweep ----
    float4 pa = pv[t * 2 + 0];
    float4 pb = pv[t * 2 + 1];
    float pvals[PER] = { pa.x, pa.y, pa.z, pa.w, pb.x, pb.y, pb.z, pb.w };

    float s1 = 0.0f, s2 = 0.0f;
    const float kbase = (float)(t * PER + 1);
#pragma unroll
    for (int i = 0; i < PER; ++i) {
        c += v[i];
        // f1 = 2*prec*rec/(prec+rec) == 2c/(k+T)   (0 cases handled since c=0 -> 0)
        float r  = __fdividef((2.0f * INV_TAU) * (float)c, kbase + (float)i + Tf);
        float e  = __expf(r);
        float lp = __logf(pvals[i]);
        s1 += e;
        s2 += e * (r - lp);
    }

    // ---- block reduce (s1, s2) ----
#pragma unroll
    for (int o = 16; o; o >>= 1) {
        s1 += __shfl_down_sync(0xffffffffu, s1, o);
        s2 += __shfl_down_sync(0xffffffffu, s2, o);
    }
    __shared__ float r1[16], r2[16];
    if (lane == 0) { r1[warp] = s1; r2[warp] = s2; }
    __syncthreads();
    if (t < 16) {
        s1 = r1[t]; s2 = r2[t];
#pragma unroll
        for (int o = 8; o; o >>= 1) {
            s1 += __shfl_down_sync(0x0000ffffu, s1, o);
            s2 += __shfl_down_sync(0x0000ffffu, s2, o);
        }
        if (t == 0)
            g_row[row] = __fdividef(s2, s1) - __logf(s1);
    }
}

// Deterministic final reduction: one block, 1024 threads
__global__ __launch_bounds__(1024)
void divloss_final_kernel(float* __restrict__ out) {
    const int t = threadIdx.x;
    float v = g_row[t];
#pragma unroll
    for (int o = 16; o; o >>= 1) v += __shfl_down_sync(0xffffffffu, v, o);
    __shared__ float sh[32];
    if ((t & 31) == 0) sh[t >> 5] = v;
    __syncthreads();
    if (t < 32) {
        float w = sh[t];
#pragma unroll
        for (int o = 16; o; o >>= 1) w += __shfl_down_sync(0xffffffffu, w, o);
        if (t == 0) out[0] = w * (1.0f / (float)B_ROWS);
    }
}

extern "C" void kernel_launch(void* const* d_in, const int* in_sizes, int n_in,
                              void* d_out, int out_size) {
    const float* p_in   = (const float*)d_in[0];   // output: (B, L, 1) float32
    const int*   labels = (const int*)  d_in[1];   // labels: (B, L) int32
    float*       out    = (float*)d_out;

    divloss_row_kernel<<<B_ROWS, THREADS>>>(p_in, labels);
    divloss_final_kernel<<<1, 1024>>>(out);
}

// round 3
// speedup vs baseline: 1.0441x; 1.0441x over previous
#include <cuda_runtime.h>
#include <cuda_bf16.h>

// Problem constants
constexpr int B_ROWS  = 1024;
constexpr int L_COLS  = 4096;
constexpr int THREADS = 512;               // threads per row-block
constexpr int PER     = L_COLS / THREADS;  // 8 elements per thread
constexpr float INV_TAU = 1.0f / 0.85f;
constexpr float A_COEF  = 2.0f * INV_TAU;  // r = A*c/(k+T)

// Per-row partial results + completion counter (no device allocs allowed)
__device__ float g_row[B_ROWS];
__device__ unsigned int g_counter;   // zero-initialized; self-resetting

__global__ __launch_bounds__(THREADS, 3)
void divloss_fused_kernel(const float* __restrict__ p_in,
                          const int*   __restrict__ lab_in,
                          float*       __restrict__ out) {
    const int row  = blockIdx.x;
    const int t    = threadIdx.x;
    const int lane = t & 31;
    const int warp = t >> 5;

    const int4*   lab = reinterpret_cast<const int4*>(lab_in + (size_t)row * L_COLS);
    const float4* pv  = reinterpret_cast<const float4*>(p_in  + (size_t)row * L_COLS);

    // ---- front-batched loads (MLP=4) ----
    int4   la = lab[t * 2 + 0];
    int4   lb = lab[t * 2 + 1];
    float4 pa = pv[t * 2 + 0];
    float4 pb = pv[t * 2 + 1];

    // pack 8 binary labels into a bitmask (saves registers)
    unsigned bits = (la.x) | (la.y << 1) | (la.z << 2) | (la.w << 3)
                  | (lb.x << 4) | (lb.y << 5) | (lb.z << 6) | (lb.w << 7);
    int local = __popc(bits);

    // ---- block scan of per-thread label counts ----
    int x = local;
#pragma unroll
    for (int o = 1; o < 32; o <<= 1) {
        int y = __shfl_up_sync(0xffffffffu, x, o);
        if (lane >= o) x += y;
    }
    __shared__ int s_warp[16];
    __shared__ int s_off[17];
    if (lane == 31) s_warp[warp] = x;
    __syncthreads();
    if (t == 0) {
        int acc = 0;
#pragma unroll
        for (int w = 0; w < 16; ++w) { s_off[w] = acc; acc += s_warp[w]; }
        s_off[16] = acc;   // total positives T
    }
    __syncthreads();

    const float Tf = (float)s_off[16];
    int c = s_off[warp] + (x - local);   // exclusive prefix count for this thread

    float pvals[PER] = { pa.x, pa.y, pa.z, pa.w, pb.x, pb.y, pb.z, pb.w };

    // ---- fused f1 / softmax-KL sweep: ONE RCP per thread ----
    // denominators are d0, d0+1, ..., d0+7 with d0 = t*8 + 1 + T
    const float d0   = (float)(t * PER + 1) + Tf;
    float s1 = 0.0f, s2 = 0.0f;

    if (d0 >= 1024.0f) {
        const float inv0 = __fdividef(1.0f, d0);
#pragma unroll
        for (int i = 0; i < PER; ++i) {
            c += (bits >> i) & 1;
            float xi   = (float)i * inv0;
            float corr = fmaf(-xi, 1.0f - xi, 1.0f);      // 1 - x + x^2
            float r    = (A_COEF * (float)c) * (inv0 * corr);
            float e    = __expf(r);
            float lp   = __logf(pvals[i]);
            s1 += e;
            s2  = fmaf(e, r - lp, s2);
        }
    } else {
        // rare small-denominator path: exact per-element divide
#pragma unroll
        for (int i = 0; i < PER; ++i) {
            c += (bits >> i) & 1;
            float r  = __fdividef(A_COEF * (float)c, d0 + (float)i);
            float e  = __expf(r);
            float lp = __logf(pvals[i]);
            s1 += e;
            s2  = fmaf(e, r - lp, s2);
        }
    }

    // ---- block reduce (s1, s2) ----
#pragma unroll
    for (int o = 16; o; o >>= 1) {
        s1 += __shfl_down_sync(0xffffffffu, s1, o);
        s2 += __shfl_down_sync(0xffffffffu, s2, o);
    }
    __shared__ float r1[16], r2[16];
    if (lane == 0) { r1[warp] = s1; r2[warp] = s2; }
    __syncthreads();

    __shared__ bool s_last;
    if (t == 0) {
        float a1 = 0.0f, a2 = 0.0f;
#pragma unroll
        for (int w = 0; w < 16; ++w) { a1 += r1[w]; a2 += r2[w]; }
        g_row[row] = __fdividef(a2, a1) - __logf(a1);
        __threadfence();
        unsigned done = atomicAdd(&g_counter, 1u);
        s_last = (done == (unsigned)(gridDim.x - 1));
    }
    __syncthreads();

    // ---- last block: deterministic final reduction of all rows ----
    if (s_last) {
        if (t == 0) g_counter = 0;   // reset for next graph replay
        float v = g_row[t] + g_row[t + THREADS];   // fixed-order pairwise
#pragma unroll
        for (int o = 16; o; o >>= 1) v += __shfl_down_sync(0xffffffffu, v, o);
        __shared__ float sh[16];
        if (lane == 0) sh[warp] = v;
        __syncthreads();
        if (t == 0) {
            float w = 0.0f;
#pragma unroll
            for (int i = 0; i < 16; ++i) w += sh[i];
            out[0] = w * (1.0f / (float)B_ROWS);
        }
    }
}

extern "C" void kernel_launch(void* const* d_in, const int* in_sizes, int n_in,
                              void* d_out, int out_size) {
    const float* p_in   = (const float*)d_in[0];   // output: (B, L, 1) float32
    const int*   labels = (const int*)  d_in[1];   // labels: (B, L) int32
    float*       out    = (float*)d_out;

    divloss_fused_kernel<<<B_ROWS, THREADS>>>(p_in, labels, out);
}

// round 7
// speedup vs baseline: 1.1250x; 1.0775x over previous
#include <cuda_runtime.h>
#include <cuda_bf16.h>

constexpr int B_ROWS  = 1024;
constexpr int L_COLS  = 4096;
constexpr int THREADS = 256;               // threads per row-block
constexpr int PER     = L_COLS / THREADS;  // 16 elements per thread
constexpr float INV_TAU = 1.0f / 0.85f;
constexpr float A_COEF  = 2.0f * INV_TAU;  // r = A*c/(k+T)

__device__ float g_row[B_ROWS];
__device__ unsigned int g_counter;   // zero-init; self-resetting

__global__ __launch_bounds__(THREADS, 6)
void divloss_fused_kernel(const float* __restrict__ p_in,
                          const int*   __restrict__ lab_in,
                          float*       __restrict__ out) {
    const int row  = blockIdx.x;
    const int t    = threadIdx.x;
    const int lane = t & 31;
    const int warp = t >> 5;

    const int4*   lab = reinterpret_cast<const int4*>(lab_in + (size_t)row * L_COLS) + t * 4;
    const float4* pv  = reinterpret_cast<const float4*>(p_in  + (size_t)row * L_COLS) + t * 4;

    // ---- front-batched loads (8x LDG.128, MLP=8) ----
    int4   l0 = lab[0], l1 = lab[1], l2 = lab[2], l3 = lab[3];
    float4 p0 = pv[0],  p1 = pv[1],  p2 = pv[2],  p3 = pv[3];

    // pack 16 binary labels into one bitmask
    unsigned bits =
         (unsigned)l0.x        | ((unsigned)l0.y << 1)  | ((unsigned)l0.z << 2)  | ((unsigned)l0.w << 3)
      | ((unsigned)l1.x << 4)  | ((unsigned)l1.y << 5)  | ((unsigned)l1.z << 6)  | ((unsigned)l1.w << 7)
      | ((unsigned)l2.x << 8)  | ((unsigned)l2.y << 9)  | ((unsigned)l2.z << 10) | ((unsigned)l2.w << 11)
      | ((unsigned)l3.x << 12) | ((unsigned)l3.y << 13) | ((unsigned)l3.z << 14) | ((unsigned)l3.w << 15);
    const int local = __popc(bits);

    // ---- warp inclusive scan of per-thread label counts ----
    int x = local;
#pragma unroll
    for (int o = 1; o < 32; o <<= 1) {
        int y = __shfl_up_sync(0xffffffffu, x, o);
        if (lane >= o) x += y;
    }
    __shared__ int s_warp[8];
    __shared__ int s_off[9];
    if (lane == 31) s_warp[warp] = x;

    // ---- hoisted: compute log(p) NOW, overlapping the scan barrier ----
    float lp[PER] = { p0.x, p0.y, p0.z, p0.w, p1.x, p1.y, p1.z, p1.w,
                      p2.x, p2.y, p2.z, p2.w, p3.x, p3.y, p3.z, p3.w };
#pragma unroll
    for (int i = 0; i < PER; ++i) lp[i] = __logf(lp[i]);

    __syncthreads();
    // warp-parallel scan of the 8 warp sums (lanes 0-7 of warp 0)
    if (t < 8) {
        int y = s_warp[t];
        int incl = y;
#pragma unroll
        for (int o = 1; o < 8; o <<= 1) {
            int z = __shfl_up_sync(0x000000ffu, incl, o);
            if (t >= o) incl += z;
        }
        s_off[t] = incl - y;          // exclusive warp offset
        if (t == 7) s_off[8] = incl;  // total positives T
    }
    __syncthreads();

    const float Tf = (float)s_off[8];
    float cf = (float)(s_off[warp] + (x - local));   // exclusive prefix count
    const float d0 = (float)(t * PER + 1) + Tf;      // first denominator

    float s1 = 0.0f, s2 = 0.0f;
    if (d0 >= 1024.0f) {
        // one RCP per thread; 1/(d0+i) = inv0*(1 - x + x^2), x = i*inv0
        const float inv0 = __fdividef(1.0f, d0);
        const float b0   = A_COEF * inv0;
#pragma unroll
        for (int i = 0; i < PER; ++i) {
            cf += ((bits >> i) & 1) ? 1.0f : 0.0f;
            float xi   = (float)i * inv0;
            float corr = fmaf(xi, xi, 1.0f) - xi;
            float r    = (cf * corr) * b0;
            float e    = __expf(r);
            s1 += e;
            s2  = fmaf(e, r - lp[i], s2);
        }
    } else {
        // rare small-T path: exact per-element divide
#pragma unroll
        for (int i = 0; i < PER; ++i) {
            cf += ((bits >> i) & 1) ? 1.0f : 0.0f;
            float r = __fdividef(A_COEF * cf, d0 + (float)i);
            float e = __expf(r);
            s1 += e;
            s2  = fmaf(e, r - lp[i], s2);
        }
    }

    // ---- block reduce (s1, s2) over 8 warps ----
#pragma unroll
    for (int o = 16; o; o >>= 1) {
        s1 += __shfl_down_sync(0xffffffffu, s1, o);
        s2 += __shfl_down_sync(0xffffffffu, s2, o);
    }
    __shared__ float r1[8], r2[8];
    if (lane == 0) { r1[warp] = s1; r2[warp] = s2; }
    __syncthreads();

    __shared__ bool s_last;
    if (t == 0) {
        float a1 = 0.0f, a2 = 0.0f;
#pragma unroll
        for (int w = 0; w < 8; ++w) { a1 += r1[w]; a2 += r2[w]; }
        g_row[row] = __fdividef(a2, a1) - __logf(a1);
        __threadfence();
        unsigned done = atomicAdd(&g_counter, 1u);
        s_last = (done == (unsigned)(B_ROWS - 1));
    }
    __syncthreads();

    // ---- last block: deterministic final reduction of all 1024 rows ----
    if (s_last) {
        if (t == 0) g_counter = 0;   // reset for graph replay
        float v = (g_row[t] + g_row[t + 256]) + (g_row[t + 512] + g_row[t + 768]);
#pragma unroll
        for (int o = 16; o; o >>= 1) v += __shfl_down_sync(0xffffffffu, v, o);
        __shared__ float sh[8];
        if (lane == 0) sh[warp] = v;
        __syncthreads();
        if (t == 0) {
            float w = 0.0f;
#pragma unroll
            for (int i = 0; i < 8; ++i) w += sh[i];
            out[0] = w * (1.0f / (float)B_ROWS);
        }
    }
}

extern "C" void kernel_launch(void* const* d_in, const int* in_sizes, int n_in,
                              void* d_out, int out_size) {
    const float* p_in   = (const float*)d_in[0];   // output: (B, L, 1) float32
    const int*   labels = (const int*)  d_in[1];   // labels: (B, L) int32
    float*       out    = (float*)d_out;

    divloss_fused_kernel<<<B_ROWS, THREADS>>>(p_in, labels, out);
}